// round 2
// baseline (speedup 1.0000x reference)
#include <cuda_runtime.h>
#include <cstdint>

// ---------------- scratch (static device globals: allowed) ----------------
#define MAXN 50000
#define MAXF 512
__device__ float g_h [MAXN * MAXF];   // h = x @ W
__device__ float g_x1[MAXN * MAXF];   // ping
__device__ float g_x2[MAXN * MAXF];   // pong
__device__ float g_dis[MAXN];         // deg -> rsqrt(deg)
__device__ float g_gate[MAXN];        // sigmoid gate per node
__device__ float g_pool[512 * 1024];  // [G, 2*512] pooled feats

// ---------------- degree / normalization ----------------
__global__ void deg_init_kernel(float* deg, int n) {
    int i = blockIdx.x * blockDim.x + threadIdx.x;
    if (i < n) deg[i] = 1.0f;   // self loop
}
__global__ void deg_acc_kernel(const int* __restrict__ ei, float* deg, int E) {
    int i = blockIdx.x * blockDim.x + threadIdx.x;
    if (i < E) atomicAdd(&deg[ei[E + i]], 1.0f);   // dst side
}
__global__ void deg_rsqrt_kernel(float* deg, int n) {
    int i = blockIdx.x * blockDim.x + threadIdx.x;
    if (i < n) deg[i] = rsqrtf(deg[i]);
}

// ---------------- GEMM: C[M,N] = A[M,K] @ B[K,N] (+bias)(+relu) ----------------
// BM=64, BN=64, BK=16, 256 threads, 4x4 microtile. N%64==0, K%16==0 required.
template<bool BIAS, bool RELU>
__global__ void gemm_kernel(const float* __restrict__ A, const float* __restrict__ B,
                            const float* __restrict__ bias, float* __restrict__ C,
                            int M, int N, int K) {
    const int BM = 64, BN = 64, BK = 16;
    __shared__ float As[BK][BM];
    __shared__ float Bs[BK][BN];
    int tid = threadIdx.x;
    int bm = blockIdx.y * BM, bn = blockIdx.x * BN;
    int ty = tid >> 4, tx = tid & 15;
    int m0 = ty * 4, n0 = tx * 4;
    float acc[4][4] = {};
    for (int kt = 0; kt < K; kt += BK) {
        for (int i = tid; i < BM * BK; i += 256) {
            int m = i / BK, k = i % BK;
            int gm = bm + m;
            As[k][m] = (gm < M) ? A[(size_t)gm * K + kt + k] : 0.0f;
        }
        for (int i = tid; i < BK * BN; i += 256) {
            int k = i / BN, n = i % BN;
            Bs[k][n] = B[(size_t)(kt + k) * N + bn + n];
        }
        __syncthreads();
        #pragma unroll
        for (int k = 0; k < BK; k++) {
            float a[4], b[4];
            #pragma unroll
            for (int i = 0; i < 4; i++) a[i] = As[k][m0 + i];
            #pragma unroll
            for (int j = 0; j < 4; j++) b[j] = Bs[k][n0 + j];
            #pragma unroll
            for (int i = 0; i < 4; i++)
                #pragma unroll
                for (int j = 0; j < 4; j++)
                    acc[i][j] += a[i] * b[j];
        }
        __syncthreads();
    }
    #pragma unroll
    for (int i = 0; i < 4; i++) {
        int gm = bm + m0 + i;
        if (gm >= M) continue;
        #pragma unroll
        for (int j = 0; j < 4; j++) {
            int gn = bn + n0 + j;
            float v = acc[i][j];
            if (BIAS) v += bias[gn];
            if (RELU) v = fmaxf(v, 0.0f);
            C[(size_t)gm * N + gn] = v;
        }
    }
}

// ---------------- self loop: out = h * dis^2 (initializes out) ----------------
__global__ void selfloop_kernel(const float* __restrict__ h, const float* __restrict__ dis,
                                float* __restrict__ out, int total4, int Fq) {
    int i = blockIdx.x * blockDim.x + threadIdx.x;
    if (i >= total4) return;
    int row = i / Fq;
    float d = dis[row];
    float s = d * d;
    float4 v = ((const float4*)h)[i];
    v.x *= s; v.y *= s; v.z *= s; v.w *= s;
    ((float4*)out)[i] = v;
}

// ---------------- edge scatter: out[dst] += h[src] * dis[s]*dis[d] ----------------
// one warp per edge, vectorized red.global.add.v4.f32 (sm_90+)
__global__ void scatter_kernel(const float* __restrict__ H, const int* __restrict__ ei,
                               const float* __restrict__ dis, float* __restrict__ out,
                               int E, int Fq) {
    int gw = (blockIdx.x * blockDim.x + threadIdx.x) >> 5;
    int lane = threadIdx.x & 31;
    if (gw >= E) return;
    int s = ei[gw];
    int d = ei[E + gw];
    float nrm = dis[s] * dis[d];
    const float4* h4 = (const float4*)(H + (size_t)s * (Fq * 4));
    float4* o4 = (float4*)(out + (size_t)d * (Fq * 4));
    for (int j = lane; j < Fq; j += 32) {
        float4 v = h4[j];
        asm volatile("red.global.add.v4.f32 [%0], {%1,%2,%3,%4};"
                     :: "l"(o4 + j), "f"(v.x * nrm), "f"(v.y * nrm),
                        "f"(v.z * nrm), "f"(v.w * nrm) : "memory");
    }
}

// ---------------- bias + relu (in place) ----------------
__global__ void bias_relu_kernel(float* __restrict__ x, const float* __restrict__ b,
                                 int total, int F) {
    int i = blockIdx.x * blockDim.x + threadIdx.x;
    if (i >= total) return;
    x[i] = fmaxf(x[i] + b[i % F], 0.0f);
}

// ---------------- gate: sigmoid(x . pw + pb), one warp per node ----------------
__global__ void gate_kernel(const float* __restrict__ x, const float* __restrict__ pw,
                            const float* __restrict__ pb, float* __restrict__ gate,
                            int N, int F) {
    int gw = (blockIdx.x * blockDim.x + threadIdx.x) >> 5;
    int lane = threadIdx.x & 31;
    if (gw >= N) return;
    const float4* x4 = (const float4*)(x + (size_t)gw * F);
    const float4* w4 = (const float4*)pw;
    float s = 0.0f;
    int Fq = F / 4;
    for (int j = lane; j < Fq; j += 32) {
        float4 a = x4[j], b = w4[j];
        s += a.x * b.x + a.y * b.y + a.z * b.z + a.w * b.w;
    }
    #pragma unroll
    for (int o = 16; o; o >>= 1) s += __shfl_xor_sync(0xffffffffu, s, o);
    if (lane == 0) gate[gw] = 1.0f / (1.0f + expf(-(s + pb[0])));
}

// ---------------- pooling: one block per graph, binary search on sorted batch ----------------
__device__ __forceinline__ int lbound(const int* a, int n, int v) {
    int lo = 0, hi = n;
    while (lo < hi) {
        int mid = (lo + hi) >> 1;
        if (a[mid] < v) lo = mid + 1; else hi = mid;
    }
    return lo;
}
__global__ void pool_kernel(const float* __restrict__ x, const float* __restrict__ gate,
                            const int* __restrict__ batch, float* __restrict__ pool,
                            int N) {
    int g = blockIdx.x;
    int start = lbound(batch, N, g);
    int end   = lbound(batch, N, g + 1);
    int f = threadIdx.x;                    // 0..255
    float s0 = 0.f, s1 = 0.f, m0 = 0.f, m1 = 0.f;
    for (int i = start; i < end; i++) {
        float w = gate[i];
        const float* row = x + (size_t)i * 512;
        float a = row[f], b = row[f + 256];
        s0 += w * a; s1 += w * b;
        m0 = fmaxf(m0, a); m1 = fmaxf(m1, b);   // relu output >= 0, empty -> 0 OK
    }
    float* pr = pool + (size_t)g * 1024;
    pr[f]        = s0; pr[f + 256] = s1;     // weighted sum part [0,512)
    pr[f + 512]  = m0; pr[f + 768] = m1;     // max part [512,1024)
}

// ---------------- launcher ----------------
extern "C" void kernel_launch(void* const* d_in, const int* in_sizes, int n_in,
                              void* d_out, int out_size) {
    const float* X0    = (const float*)d_in[0];
    const int*   EI    = (const int*)d_in[1];     // int32 (jax default x64-disabled)
    const int*   BATCH = (const int*)d_in[2];
    const float* W1 = (const float*)d_in[3];  const float* b1 = (const float*)d_in[4];
    const float* W2 = (const float*)d_in[5];  const float* b2 = (const float*)d_in[6];
    const float* W3 = (const float*)d_in[7];  const float* b3 = (const float*)d_in[8];
    const float* pw = (const float*)d_in[9];  const float* pb = (const float*)d_in[10];
    const float* Wo = (const float*)d_in[11]; const float* bo = (const float*)d_in[12];
    float* OUT = (float*)d_out;

    int N = in_sizes[2];          // 50000 nodes
    int E = in_sizes[1] / 2;      // 800000 edges

    float *h, *x1, *x2, *dis, *gate, *pool;
    cudaGetSymbolAddress((void**)&h,    g_h);
    cudaGetSymbolAddress((void**)&x1,   g_x1);
    cudaGetSymbolAddress((void**)&x2,   g_x2);
    cudaGetSymbolAddress((void**)&dis,  g_dis);
    cudaGetSymbolAddress((void**)&gate, g_gate);
    cudaGetSymbolAddress((void**)&pool, g_pool);

    const int TB = 256;

    // --- degree + rsqrt ---
    deg_init_kernel<<<(N + TB - 1) / TB, TB>>>(dis, N);
    deg_acc_kernel<<<(E + TB - 1) / TB, TB>>>(EI, dis, E);
    deg_rsqrt_kernel<<<(N + TB - 1) / TB, TB>>>(dis, N);

    int scatterBlocks = (E * 32 + TB - 1) / TB;

    // --- layer 1: 256 -> 256 ---
    {
        int F = 256, K = 256, Fq = F / 4;
        gemm_kernel<false,false><<<dim3(F / 64, (N + 63) / 64), TB>>>(X0, W1, nullptr, h, N, F, K);
        selfloop_kernel<<<(N * Fq + TB - 1) / TB, TB>>>(h, dis, x1, N * Fq, Fq);
        scatter_kernel<<<scatterBlocks, TB>>>(h, EI, dis, x1, E, Fq);
        bias_relu_kernel<<<(N * F + TB - 1) / TB, TB>>>(x1, b1, N * F, F);
    }
    // --- layer 2: 256 -> 256 ---
    {
        int F = 256, K = 256, Fq = F / 4;
        gemm_kernel<false,false><<<dim3(F / 64, (N + 63) / 64), TB>>>(x1, W2, nullptr, h, N, F, K);
        selfloop_kernel<<<(N * Fq + TB - 1) / TB, TB>>>(h, dis, x2, N * Fq, Fq);
        scatter_kernel<<<scatterBlocks, TB>>>(h, EI, dis, x2, E, Fq);
        bias_relu_kernel<<<(N * F + TB - 1) / TB, TB>>>(x2, b2, N * F, F);
    }
    // --- layer 3: 256 -> 512 ---
    {
        int F = 512, K = 256, Fq = F / 4;
        gemm_kernel<false,false><<<dim3(F / 64, (N + 63) / 64), TB>>>(x2, W3, nullptr, h, N, F, K);
        selfloop_kernel<<<(N * Fq + TB - 1) / TB, TB>>>(h, dis, x1, N * Fq, Fq);
        scatter_kernel<<<scatterBlocks, TB>>>(h, EI, dis, x1, E, Fq);
        bias_relu_kernel<<<(N * F + TB - 1) / TB, TB>>>(x1, b3, N * F, F);
    }

    // --- gate + pooling ---
    gate_kernel<<<(N * 32 + TB - 1) / TB, TB>>>(x1, pw, pb, gate, N, 512);
    pool_kernel<<<512, 256>>>(x1, gate, BATCH, pool, N);

    // --- head: [512,1024] @ [1024,2048] + bo, relu ---
    gemm_kernel<true,true><<<dim3(2048 / 64, 512 / 64), TB>>>(pool, Wo, bo, OUT, 512, 2048, 1024);
}

// round 4
// speedup vs baseline: 2.0159x; 2.0159x over previous
#include <cuda_runtime.h>
#include <cstdint>

// ---------------- scratch ----------------
#define MAXN 50000
#define MAXF 512
#define MAXE 800000
__device__ float g_h [MAXN * MAXF];     // h = x @ W
__device__ float g_x1[MAXN * MAXF];     // ping
__device__ float g_x2[MAXN * MAXF];     // pong
__device__ float g_dis[MAXN];           // rsqrt(deg)
__device__ float g_gate[MAXN];
__device__ float g_pool[512 * 1024];
__device__ int   g_cnt [MAXN];          // in-degree (no self loop)
__device__ int   g_fill[MAXN];
__device__ int   g_rowptr[MAXN + 1];
__device__ int   g_csr[MAXE];           // src ids grouped by dst
__device__ int   g_bsum[64];            // scan block sums

// ---------------- CSR build ----------------
__global__ void init_kernel(int* cnt, int* fill, int n) {
    int i = blockIdx.x * blockDim.x + threadIdx.x;
    if (i < n) { cnt[i] = 0; fill[i] = 0; }
}
__global__ void count_kernel(const int* __restrict__ ei, int* cnt, int E) {
    int i = blockIdx.x * blockDim.x + threadIdx.x;
    if (i < E) atomicAdd(&cnt[ei[E + i]], 1);
}
__global__ void dis_kernel(const int* __restrict__ cnt, float* dis, int n) {
    int i = blockIdx.x * blockDim.x + threadIdx.x;
    if (i < n) dis[i] = rsqrtf((float)cnt[i] + 1.0f);
}
__global__ void scan1_kernel(const int* __restrict__ cnt, int* __restrict__ excl,
                             int* __restrict__ bsum, int n) {
    __shared__ int wsum[32];
    int tid = threadIdx.x;
    int i = blockIdx.x * 1024 + tid;
    int v = (i < n) ? cnt[i] : 0;
    int lane = tid & 31, wid = tid >> 5;
    int x = v;
    #pragma unroll
    for (int o = 1; o < 32; o <<= 1) {
        int t = __shfl_up_sync(0xffffffffu, x, o);
        if (lane >= o) x += t;
    }
    if (lane == 31) wsum[wid] = x;
    __syncthreads();
    if (wid == 0) {
        int w = wsum[lane];
        #pragma unroll
        for (int o = 1; o < 32; o <<= 1) {
            int t = __shfl_up_sync(0xffffffffu, w, o);
            if (lane >= o) w += t;
        }
        wsum[lane] = w;
    }
    __syncthreads();
    int woff = (wid > 0) ? wsum[wid - 1] : 0;
    if (i < n) excl[i] = x - v + woff;
    if (tid == 1023) bsum[blockIdx.x] = x + woff;
}
__global__ void scan2_kernel(int* bsum, int nb) {
    int run = 0;
    for (int b = 0; b < nb; b++) { int t = bsum[b]; bsum[b] = run; run += t; }
}
__global__ void scan3_kernel(int* excl, const int* __restrict__ bsum, int n, int E) {
    int i = blockIdx.x * 1024 + threadIdx.x;
    if (i < n) excl[i] += bsum[blockIdx.x];
    if (i == 0) excl[n] = E;
}
__global__ void fill_kernel(const int* __restrict__ ei, const int* __restrict__ rowptr,
                            int* fill, int* __restrict__ csr, int E) {
    int e = blockIdx.x * blockDim.x + threadIdx.x;
    if (e >= E) return;
    int d = ei[E + e];
    int pos = atomicAdd(&fill[d], 1);
    csr[rowptr[d] + pos] = ei[e];
}

// ---------------- GEMM: 128x128x8, 8x8 microtile, float4 everywhere ----------------
template<bool BIAS, bool RELU>
__launch_bounds__(256, 2)
__global__ void gemm_kernel(const float* __restrict__ A, const float* __restrict__ B,
                            const float* __restrict__ bias, float* __restrict__ C,
                            int M, int N, int K) {
    const int BM = 128, BN = 128, BK = 8;
    __shared__ float As[BK][BM];
    __shared__ float Bs[BK][BN];
    int tid = threadIdx.x;
    int bm = blockIdx.y * BM, bn = blockIdx.x * BN;
    int ty = tid >> 4, tx = tid & 15;
    int m0 = ty * 8, n0 = tx * 8;
    int arow = tid >> 1, ak = (tid & 1) * 4;     // A: 128 rows x 8 k
    int brow = tid >> 5, bcol = (tid & 31) * 4;  // B: 8 rows x 128 n
    float acc[8][8] = {};
    for (int kt = 0; kt < K; kt += BK) {
        int gm = bm + arow;
        float4 av = (gm < M) ? *(const float4*)(A + (size_t)gm * K + kt + ak)
                             : make_float4(0.f, 0.f, 0.f, 0.f);
        As[ak + 0][arow] = av.x; As[ak + 1][arow] = av.y;
        As[ak + 2][arow] = av.z; As[ak + 3][arow] = av.w;
        *(float4*)&Bs[brow][bcol] = *(const float4*)(B + (size_t)(kt + brow) * N + bn + bcol);
        __syncthreads();
        #pragma unroll
        for (int k = 0; k < BK; k++) {
            float a[8], b[8];
            *(float4*)(a)     = *(float4*)&As[k][m0];
            *(float4*)(a + 4) = *(float4*)&As[k][m0 + 4];
            *(float4*)(b)     = *(float4*)&Bs[k][n0];
            *(float4*)(b + 4) = *(float4*)&Bs[k][n0 + 4];
            #pragma unroll
            for (int i = 0; i < 8; i++)
                #pragma unroll
                for (int j = 0; j < 8; j++)
                    acc[i][j] += a[i] * b[j];
        }
        __syncthreads();
    }
    #pragma unroll
    for (int i = 0; i < 8; i++) {
        int gm = bm + m0 + i;
        if (gm >= M) continue;
        #pragma unroll
        for (int jq = 0; jq < 2; jq++) {
            int gn = bn + n0 + jq * 4;
            float4 v = make_float4(acc[i][jq*4+0], acc[i][jq*4+1], acc[i][jq*4+2], acc[i][jq*4+3]);
            if (BIAS) {
                float4 bb = *(const float4*)(bias + gn);
                v.x += bb.x; v.y += bb.y; v.z += bb.z; v.w += bb.w;
            }
            if (RELU) {
                v.x = fmaxf(v.x, 0.f); v.y = fmaxf(v.y, 0.f);
                v.z = fmaxf(v.z, 0.f); v.w = fmaxf(v.w, 0.f);
            }
            *(float4*)(C + (size_t)gm * N + gn) = v;
        }
    }
}

// ---------------- fused aggregation: self-loop + neighbor gather + bias + relu ----------------
// one warp per node; V = float4 per lane (V*128 = F)
template<int V>
__global__ void gather_kernel(const float* __restrict__ H, const int* __restrict__ rowptr,
                              const int* __restrict__ csr, const float* __restrict__ dis,
                              const float* __restrict__ bias, float* __restrict__ out, int N) {
    int gw = (blockIdx.x * blockDim.x + threadIdx.x) >> 5;
    int lane = threadIdx.x & 31;
    if (gw >= N) return;
    const int FQ = V * 32;
    float dd = dis[gw];
    float sw = dd * dd;
    const float4* hrow = (const float4*)H + (size_t)gw * FQ;
    float4 acc[V];
    #pragma unroll
    for (int v = 0; v < V; v++) {
        float4 t = hrow[lane + 32 * v];
        acc[v] = make_float4(t.x * sw, t.y * sw, t.z * sw, t.w * sw);
    }
    int r0 = rowptr[gw], r1 = rowptr[gw + 1];
    for (int e = r0; e < r1; e++) {
        int s = csr[e];
        float w = dis[s] * dd;
        const float4* hs = (const float4*)H + (size_t)s * FQ;
        #pragma unroll
        for (int v = 0; v < V; v++) {
            float4 t = hs[lane + 32 * v];
            acc[v].x += t.x * w; acc[v].y += t.y * w;
            acc[v].z += t.z * w; acc[v].w += t.w * w;
        }
    }
    float4* orow = (float4*)out + (size_t)gw * FQ;
    const float4* b4 = (const float4*)bias;
    #pragma unroll
    for (int v = 0; v < V; v++) {
        float4 b = b4[lane + 32 * v];
        float4 r;
        r.x = fmaxf(acc[v].x + b.x, 0.f); r.y = fmaxf(acc[v].y + b.y, 0.f);
        r.z = fmaxf(acc[v].z + b.z, 0.f); r.w = fmaxf(acc[v].w + b.w, 0.f);
        orow[lane + 32 * v] = r;
    }
}

// ---------------- gate: sigmoid(x . pw + pb) ----------------
__global__ void gate_kernel(const float* __restrict__ x, const float* __restrict__ pw,
                            const float* __restrict__ pb, float* __restrict__ gate,
                            int N, int F) {
    int gw = (blockIdx.x * blockDim.x + threadIdx.x) >> 5;
    int lane = threadIdx.x & 31;
    if (gw >= N) return;
    const float4* x4 = (const float4*)(x + (size_t)gw * F);
    const float4* w4 = (const float4*)pw;
    float s = 0.0f;
    int Fq = F / 4;
    for (int j = lane; j < Fq; j += 32) {
        float4 a = x4[j], b = w4[j];
        s += a.x * b.x + a.y * b.y + a.z * b.z + a.w * b.w;
    }
    #pragma unroll
    for (int o = 16; o; o >>= 1) s += __shfl_xor_sync(0xffffffffu, s, o);
    if (lane == 0) gate[gw] = 1.0f / (1.0f + expf(-(s + pb[0])));
}

// ---------------- pooling ----------------
__device__ __forceinline__ int lbound(const int* a, int n, int v) {
    int lo = 0, hi = n;
    while (lo < hi) {
        int mid = (lo + hi) >> 1;
        if (a[mid] < v) lo = mid + 1; else hi = mid;
    }
    return lo;
}
__global__ void pool_kernel(const float* __restrict__ x, const float* __restrict__ gate,
                            const int* __restrict__ batch, float* __restrict__ pool,
                            int N) {
    int g = blockIdx.x;
    int start = lbound(batch, N, g);
    int end   = lbound(batch, N, g + 1);
    int f = threadIdx.x;
    float s0 = 0.f, s1 = 0.f, m0 = 0.f, m1 = 0.f;
    for (int i = start; i < end; i++) {
        float w = gate[i];
        const float* row = x + (size_t)i * 512;
        float a = row[f], b = row[f + 256];
        s0 += w * a; s1 += w * b;
        m0 = fmaxf(m0, a); m1 = fmaxf(m1, b);
    }
    float* pr = pool + (size_t)g * 1024;
    pr[f]       = s0; pr[f + 256] = s1;
    pr[f + 512] = m0; pr[f + 768] = m1;
}

// ---------------- launcher ----------------
extern "C" void kernel_launch(void* const* d_in, const int* in_sizes, int n_in,
                              void* d_out, int out_size) {
    const float* X0    = (const float*)d_in[0];
    const int*   EI    = (const int*)d_in[1];
    const int*   BATCH = (const int*)d_in[2];
    const float* W1 = (const float*)d_in[3];  const float* b1 = (const float*)d_in[4];
    const float* W2 = (const float*)d_in[5];  const float* b2 = (const float*)d_in[6];
    const float* W3 = (const float*)d_in[7];  const float* b3 = (const float*)d_in[8];
    const float* pw = (const float*)d_in[9];  const float* pb = (const float*)d_in[10];
    const float* Wo = (const float*)d_in[11]; const float* bo = (const float*)d_in[12];
    float* OUT = (float*)d_out;

    int N = in_sizes[2];
    int E = in_sizes[1] / 2;

    float *h, *x1, *x2, *dis, *gate, *pool;
    int *cnt, *fill, *rowptr, *csr, *bsum;
    cudaGetSymbolAddress((void**)&h,    g_h);
    cudaGetSymbolAddress((void**)&x1,   g_x1);
    cudaGetSymbolAddress((void**)&x2,   g_x2);
    cudaGetSymbolAddress((void**)&dis,  g_dis);
    cudaGetSymbolAddress((void**)&gate, g_gate);
    cudaGetSymbolAddress((void**)&pool, g_pool);
    cudaGetSymbolAddress((void**)&cnt,  g_cnt);
    cudaGetSymbolAddress((void**)&fill, g_fill);
    cudaGetSymbolAddress((void**)&rowptr, g_rowptr);
    cudaGetSymbolAddress((void**)&csr,  g_csr);
    cudaGetSymbolAddress((void**)&bsum, g_bsum);

    const int TB = 256;
    int nScanBlocks = (N + 1023) / 1024;

    // --- CSR build + normalization ---
    init_kernel<<<(N + TB - 1) / TB, TB>>>(cnt, fill, N);
    count_kernel<<<(E + TB - 1) / TB, TB>>>(EI, cnt, E);
    dis_kernel<<<(N + TB - 1) / TB, TB>>>(cnt, dis, N);
    scan1_kernel<<<nScanBlocks, 1024>>>(cnt, rowptr, bsum, N);
    scan2_kernel<<<1, 1>>>(bsum, nScanBlocks);
    scan3_kernel<<<nScanBlocks, 1024>>>(rowptr, bsum, N, E);
    fill_kernel<<<(E + TB - 1) / TB, TB>>>(EI, rowptr, fill, csr, E);

    int gatherBlocks = (N * 32 + TB - 1) / TB;

    // --- layer 1: 256 -> 256 ---
    gemm_kernel<false,false><<<dim3(256/128, (N+127)/128), TB>>>(X0, W1, nullptr, h, N, 256, 256);
    gather_kernel<2><<<gatherBlocks, TB>>>(h, rowptr, csr, dis, b1, x1, N);
    // --- layer 2: 256 -> 256 ---
    gemm_kernel<false,false><<<dim3(256/128, (N+127)/128), TB>>>(x1, W2, nullptr, h, N, 256, 256);
    gather_kernel<2><<<gatherBlocks, TB>>>(h, rowptr, csr, dis, b2, x2, N);
    // --- layer 3: 256 -> 512 ---
    gemm_kernel<false,false><<<dim3(512/128, (N+127)/128), TB>>>(x2, W3, nullptr, h, N, 512, 256);
    gather_kernel<4><<<gatherBlocks, TB>>>(h, rowptr, csr, dis, b3, x1, N);

    // --- gate + pooling ---
    gate_kernel<<<(N * 32 + TB - 1) / TB, TB>>>(x1, pw, pb, gate, N, 512);
    pool_kernel<<<512, 256>>>(x1, gate, BATCH, pool, N);

    // --- head: [512,1024] @ [1024,2048] ---
    gemm_kernel<true,true><<<dim3(2048/128, 512/128), TB>>>(pool, Wo, bo, OUT, 512, 2048, 1024);
}